// round 3
// baseline (speedup 1.0000x reference)
#include <cuda_runtime.h>

// StructureEncoder: B=524288 elems, 24-joint tree of tiny MLPs (10->10->6).
// R3: occupancy-first redesign. No smem element buffer (weights only, 21.5KB)
// -> 2 CTAs x 256 threads/SM. E=2 elems/thread shares every weight broadcast.
// quat read per-joint via LDG.128 (L1-cached line reuse), feats stored
// per-joint via 3x STG.64 (write-merge in L2). Branch-parent feats (joints
// 0 and 9) saved/restored in registers. fma.rn.f32x2 packed math throughout.

#define THREADS 256
#define WJ      224      // padded weight floats per joint
#define NJ      24

typedef unsigned long long u64;

__device__ __forceinline__ u64 pk(float a, float b) {
    u64 r; asm("mov.b64 %0,{%1,%2};" : "=l"(r) : "f"(a), "f"(b)); return r;
}
__device__ __forceinline__ void upk(u64 v, float& a, float& b) {
    asm("mov.b64 {%0,%1},%2;" : "=f"(a), "=f"(b) : "l"(v));
}
__device__ __forceinline__ u64 ffma2(u64 a, u64 b, u64 c) {
    u64 d; asm("fma.rn.f32x2 %0,%1,%2,%3;" : "=l"(d) : "l"(a), "l"(b), "l"(c)); return d;
}

// Padded per-joint weight block in smem (base = j*WJ floats, 16B-aligned):
//   [  0..119]  W1 rows r=0..9 (r<4: W1a row r, else W1b row r-4), 12 floats/row
//   [120..131]  b1 (10 + 2 pad)
//   [132..211]  W2 rows k=0..9, 8 floats/row (6 data + 2 pad)
//   [212..219]  b2 (6 + 2 pad)
//   [220..223]  pad

template<int J, bool ROOT>
__device__ __forceinline__ void joint_step(const float* __restrict__ wts,
                                           const float4* __restrict__ qA4,
                                           const float4* __restrict__ qB4,
                                           float* __restrict__ outA,
                                           float* __restrict__ outB,
                                           float (&pfA)[6], float (&pfB)[6])
{
    const int jb = J * WJ;

    float4 qa = qA4[J];       // quat[eA][J][0..3]  (L1-resident line)
    float4 qb = qB4[J];

    float xA[10], xB[10];
    xA[0]=qa.x; xA[1]=qa.y; xA[2]=qa.z; xA[3]=qa.w;
    xB[0]=qb.x; xB[1]=qb.y; xB[2]=qb.z; xB[3]=qb.w;
    if (!ROOT) {
        #pragma unroll
        for (int c = 0; c < 6; c++) { xA[4+c] = pfA[c]; xB[4+c] = pfB[c]; }
    }

    // ---- layer 1: h = relu(x @ W1 + b1), 10 outputs = 5 f32x2 accumulators ----
    ulonglong2 bA = *(const ulonglong2*)(wts + jb + 120);  // b1[0..3]
    ulonglong2 bB = *(const ulonglong2*)(wts + jb + 124);  // b1[4..7]
    u64        bC = *(const u64*)       (wts + jb + 128);  // b1[8..9]
    u64 hA0=bA.x, hA1=bA.y, hA2=bB.x, hA3=bB.y, hA4=bC;
    u64 hB0=bA.x, hB1=bA.y, hB2=bB.x, hB3=bB.y, hB4=bC;

    const int NR = ROOT ? 4 : 10;
    #pragma unroll
    for (int r = 0; r < NR; r++) {
        ulonglong2 wAB = *(const ulonglong2*)(wts + jb + r*12);      // W1[r][0..3]
        ulonglong2 wCD = *(const ulonglong2*)(wts + jb + r*12 + 4);  // W1[r][4..7]
        u64        wE  = *(const u64*)       (wts + jb + r*12 + 8);  // W1[r][8..9]
        u64 xa = pk(xA[r], xA[r]);
        hA0 = ffma2(xa, wAB.x, hA0); hA1 = ffma2(xa, wAB.y, hA1);
        hA2 = ffma2(xa, wCD.x, hA2); hA3 = ffma2(xa, wCD.y, hA3);
        hA4 = ffma2(xa, wE,    hA4);
        u64 xb = pk(xB[r], xB[r]);
        hB0 = ffma2(xb, wAB.x, hB0); hB1 = ffma2(xb, wAB.y, hB1);
        hB2 = ffma2(xb, wCD.x, hB2); hB3 = ffma2(xb, wCD.y, hB3);
        hB4 = ffma2(xb, wE,    hB4);
    }

    float sA[10], sB[10];
    {
        float a, b;
        upk(hA0,a,b); sA[0]=fmaxf(a,0.f); sA[1]=fmaxf(b,0.f);
        upk(hA1,a,b); sA[2]=fmaxf(a,0.f); sA[3]=fmaxf(b,0.f);
        upk(hA2,a,b); sA[4]=fmaxf(a,0.f); sA[5]=fmaxf(b,0.f);
        upk(hA3,a,b); sA[6]=fmaxf(a,0.f); sA[7]=fmaxf(b,0.f);
        upk(hA4,a,b); sA[8]=fmaxf(a,0.f); sA[9]=fmaxf(b,0.f);
        upk(hB0,a,b); sB[0]=fmaxf(a,0.f); sB[1]=fmaxf(b,0.f);
        upk(hB1,a,b); sB[2]=fmaxf(a,0.f); sB[3]=fmaxf(b,0.f);
        upk(hB2,a,b); sB[4]=fmaxf(a,0.f); sB[5]=fmaxf(b,0.f);
        upk(hB3,a,b); sB[6]=fmaxf(a,0.f); sB[7]=fmaxf(b,0.f);
        upk(hB4,a,b); sB[8]=fmaxf(a,0.f); sB[9]=fmaxf(b,0.f);
    }

    // ---- layer 2: feat = relu(h @ W2 + b2), 6 outputs = 3 f32x2 accumulators ----
    ulonglong2 c01 = *(const ulonglong2*)(wts + jb + 212);  // b2[0..3]
    u64        c2  = *(const u64*)       (wts + jb + 216);  // b2[4..5]
    u64 fA0=c01.x, fA1=c01.y, fA2=c2;
    u64 fB0=c01.x, fB1=c01.y, fB2=c2;

    #pragma unroll
    for (int k = 0; k < 10; k++) {
        ulonglong2 v01 = *(const ulonglong2*)(wts + jb + 132 + k*8);  // W2[k][0..3]
        u64        v2  = *(const u64*)       (wts + jb + 136 + k*8);  // W2[k][4..5]
        u64 da = pk(sA[k], sA[k]);
        fA0 = ffma2(da, v01.x, fA0); fA1 = ffma2(da, v01.y, fA1); fA2 = ffma2(da, v2, fA2);
        u64 db = pk(sB[k], sB[k]);
        fB0 = ffma2(db, v01.x, fB0); fB1 = ffma2(db, v01.y, fB1); fB2 = ffma2(db, v2, fB2);
    }

    {
        float a, b;
        upk(fA0,a,b); pfA[0]=fmaxf(a,0.f); pfA[1]=fmaxf(b,0.f);
        upk(fA1,a,b); pfA[2]=fmaxf(a,0.f); pfA[3]=fmaxf(b,0.f);
        upk(fA2,a,b); pfA[4]=fmaxf(a,0.f); pfA[5]=fmaxf(b,0.f);
        upk(fB0,a,b); pfB[0]=fmaxf(a,0.f); pfB[1]=fmaxf(b,0.f);
        upk(fB1,a,b); pfB[2]=fmaxf(a,0.f); pfB[3]=fmaxf(b,0.f);
        upk(fB2,a,b); pfB[4]=fmaxf(a,0.f); pfB[5]=fmaxf(b,0.f);
    }

    // store this joint's 6 output floats for both elems (L2 merges sectors)
    *(float2*)(outA + 6*J)     = make_float2(pfA[0], pfA[1]);
    *(float2*)(outA + 6*J + 2) = make_float2(pfA[2], pfA[3]);
    *(float2*)(outA + 6*J + 4) = make_float2(pfA[4], pfA[5]);
    *(float2*)(outB + 6*J)     = make_float2(pfB[0], pfB[1]);
    *(float2*)(outB + 6*J + 2) = make_float2(pfB[2], pfB[3]);
    *(float2*)(outB + 6*J + 4) = make_float2(pfB[4], pfB[5]);
}

__global__ void __launch_bounds__(THREADS, 2)
se_kernel(const float* __restrict__ quat, const float* __restrict__ W1a,
          const float* __restrict__ W1b, const float* __restrict__ b1,
          const float* __restrict__ W2,  const float* __restrict__ b2,
          float* __restrict__ out)
{
    __shared__ __align__(16) float wts[NJ * WJ];
    const int tid = threadIdx.x;

    // ---- stage weights into padded smem layout ----
    for (int i = tid; i < NJ * WJ; i += THREADS) {
        int j = i / WJ, o = i - j * WJ;
        float v = 0.f;
        if (o < 120) {
            int r = o / 12, k = o - r * 12;
            if (k < 10) v = (r < 4) ? W1a[j*40 + r*10 + k] : W1b[j*60 + (r-4)*10 + k];
        } else if (o < 132) {
            int t = o - 120; if (t < 10) v = b1[j*10 + t];
        } else if (o < 212) {
            int t = o - 132; int k = t / 8, c = t - k * 8;
            if (c < 6) v = W2[j*60 + k*6 + c];
        } else if (o < 220) {
            int t = o - 212; if (t < 6) v = b2[j*6 + t];
        }
        wts[i] = v;
    }
    __syncthreads();

    // elems handled by this thread: eA = blk*512 + tid, eB = eA + 256
    const int eA = blockIdx.x * (2 * THREADS) + tid;
    const int eB = eA + THREADS;
    const float4* qA4 = (const float4*)(quat + (size_t)eA * 96);
    const float4* qB4 = (const float4*)(quat + (size_t)eB * 96);
    float* outA = out + (size_t)eA * 144;
    float* outB = out + (size_t)eB * 144;

    float pfA[6], pfB[6];
    float s0A[6], s0B[6];   // feat of joint 0 (children 1,2,3)
    float s9A[6], s9B[6];   // feat of joint 9 (children 12,13,14)

    // ---- DFS over joint tree; parent feats live in registers ----
    joint_step< 0, true >(wts, qA4, qB4, outA, outB, pfA, pfB);
    #pragma unroll
    for (int c = 0; c < 6; c++) { s0A[c] = pfA[c]; s0B[c] = pfB[c]; }

    joint_step< 1, false>(wts, qA4, qB4, outA, outB, pfA, pfB);
    joint_step< 4, false>(wts, qA4, qB4, outA, outB, pfA, pfB);
    joint_step< 7, false>(wts, qA4, qB4, outA, outB, pfA, pfB);
    joint_step<10, false>(wts, qA4, qB4, outA, outB, pfA, pfB);

    #pragma unroll
    for (int c = 0; c < 6; c++) { pfA[c] = s0A[c]; pfB[c] = s0B[c]; }
    joint_step< 2, false>(wts, qA4, qB4, outA, outB, pfA, pfB);
    joint_step< 5, false>(wts, qA4, qB4, outA, outB, pfA, pfB);
    joint_step< 8, false>(wts, qA4, qB4, outA, outB, pfA, pfB);
    joint_step<11, false>(wts, qA4, qB4, outA, outB, pfA, pfB);

    #pragma unroll
    for (int c = 0; c < 6; c++) { pfA[c] = s0A[c]; pfB[c] = s0B[c]; }
    joint_step< 3, false>(wts, qA4, qB4, outA, outB, pfA, pfB);
    joint_step< 6, false>(wts, qA4, qB4, outA, outB, pfA, pfB);
    joint_step< 9, false>(wts, qA4, qB4, outA, outB, pfA, pfB);
    #pragma unroll
    for (int c = 0; c < 6; c++) { s9A[c] = pfA[c]; s9B[c] = pfB[c]; }
    joint_step<12, false>(wts, qA4, qB4, outA, outB, pfA, pfB);
    joint_step<15, false>(wts, qA4, qB4, outA, outB, pfA, pfB);

    #pragma unroll
    for (int c = 0; c < 6; c++) { pfA[c] = s9A[c]; pfB[c] = s9B[c]; }
    joint_step<13, false>(wts, qA4, qB4, outA, outB, pfA, pfB);
    joint_step<16, false>(wts, qA4, qB4, outA, outB, pfA, pfB);
    joint_step<18, false>(wts, qA4, qB4, outA, outB, pfA, pfB);
    joint_step<20, false>(wts, qA4, qB4, outA, outB, pfA, pfB);
    joint_step<22, false>(wts, qA4, qB4, outA, outB, pfA, pfB);

    #pragma unroll
    for (int c = 0; c < 6; c++) { pfA[c] = s9A[c]; pfB[c] = s9B[c]; }
    joint_step<14, false>(wts, qA4, qB4, outA, outB, pfA, pfB);
    joint_step<17, false>(wts, qA4, qB4, outA, outB, pfA, pfB);
    joint_step<19, false>(wts, qA4, qB4, outA, outB, pfA, pfB);
    joint_step<21, false>(wts, qA4, qB4, outA, outB, pfA, pfB);
    joint_step<23, false>(wts, qA4, qB4, outA, outB, pfA, pfB);
}

extern "C" void kernel_launch(void* const* d_in, const int* in_sizes, int n_in,
                              void* d_out, int out_size)
{
    const float* quat = (const float*)d_in[0];
    const float* W1a  = (const float*)d_in[1];
    const float* W1b  = (const float*)d_in[2];
    const float* b1   = (const float*)d_in[3];
    const float* W2   = (const float*)d_in[4];
    const float* b2   = (const float*)d_in[5];
    float* out = (float*)d_out;

    int B = in_sizes[0] / 96;                 // quat = B * 24 * 4 floats
    int blocks = B / (2 * THREADS);           // 524288 / 512 = 1024

    se_kernel<<<blocks, THREADS>>>(quat, W1a, W1b, b1, W2, b2, out);
}

// round 4
// speedup vs baseline: 1.7780x; 1.7780x over previous
#include <cuda_runtime.h>

// StructureEncoder: B=524288 elems, 24-joint tree of tiny MLPs (10->10->6).
// R4: two-phase smem output stager. DFS phase 1 completes joints 0..11 (output
// cols 0..71), flush (sector-aligned 288B/elem), reuse buffer for joints 12..23,
// flush cols 72..143. Buffer halves to 75.8KB -> 2 CTAs x 256 thr = 16 warps/SM.
// E=1 elem/thread, fma.rn.f32x2 packed math, weights in smem padded for direct
// u64/ulonglong2 operand loads, quat read straight from gmem (L1 line reuse).

#define THREADS 256
#define RS      74       // floats per elem row in smem stager (72 data + 2 pad)
#define WJ      224      // padded weight floats per joint
#define NJ      24

typedef unsigned long long u64;

__device__ __forceinline__ u64 pk(float a, float b) {
    u64 r; asm("mov.b64 %0,{%1,%2};" : "=l"(r) : "f"(a), "f"(b)); return r;
}
__device__ __forceinline__ void upk(u64 v, float& a, float& b) {
    asm("mov.b64 {%0,%1},%2;" : "=f"(a), "=f"(b) : "l"(v));
}
__device__ __forceinline__ u64 ffma2(u64 a, u64 b, u64 c) {
    u64 d; asm("fma.rn.f32x2 %0,%1,%2,%3;" : "=l"(d) : "l"(a), "l"(b), "l"(c)); return d;
}

// Padded per-joint weight block in smem (base = j*WJ floats, 16B-aligned):
//   [  0..119]  W1 rows r=0..9 (r<4: W1a row r, else W1b row r-4), 12 floats/row
//   [120..131]  b1 (10 + 2 pad)
//   [132..211]  W2 rows k=0..9, 8 floats/row (6 data + 2 pad)
//   [212..219]  b2 (6 + 2 pad)

template<int J, bool ROOT>
__device__ __forceinline__ void joint_step(const float* __restrict__ wts,
                                           const float4* __restrict__ q4,
                                           float* __restrict__ row,
                                           float (&pf)[6])
{
    const int jb = J * WJ;
    float4 q = q4[J];                       // quat[e][J][0..3], L1-resident line

    float x[10];
    x[0]=q.x; x[1]=q.y; x[2]=q.z; x[3]=q.w;
    if (!ROOT) {
        #pragma unroll
        for (int c = 0; c < 6; c++) x[4+c] = pf[c];
    }

    // ---- layer 1: h = relu(x @ W1 + b1), 10 outputs = 5 f32x2 accumulators ----
    ulonglong2 bA = *(const ulonglong2*)(wts + jb + 120);
    ulonglong2 bB = *(const ulonglong2*)(wts + jb + 124);
    u64        bC = *(const u64*)       (wts + jb + 128);
    u64 h0=bA.x, h1=bA.y, h2=bB.x, h3=bB.y, h4=bC;

    const int NR = ROOT ? 4 : 10;
    #pragma unroll
    for (int r = 0; r < NR; r++) {
        ulonglong2 wAB = *(const ulonglong2*)(wts + jb + r*12);
        ulonglong2 wCD = *(const ulonglong2*)(wts + jb + r*12 + 4);
        u64        wE  = *(const u64*)       (wts + jb + r*12 + 8);
        u64 xr = pk(x[r], x[r]);
        h0 = ffma2(xr, wAB.x, h0); h1 = ffma2(xr, wAB.y, h1);
        h2 = ffma2(xr, wCD.x, h2); h3 = ffma2(xr, wCD.y, h3);
        h4 = ffma2(xr, wE,    h4);
    }

    float s[10];
    {
        float a, b;
        upk(h0,a,b); s[0]=fmaxf(a,0.f); s[1]=fmaxf(b,0.f);
        upk(h1,a,b); s[2]=fmaxf(a,0.f); s[3]=fmaxf(b,0.f);
        upk(h2,a,b); s[4]=fmaxf(a,0.f); s[5]=fmaxf(b,0.f);
        upk(h3,a,b); s[6]=fmaxf(a,0.f); s[7]=fmaxf(b,0.f);
        upk(h4,a,b); s[8]=fmaxf(a,0.f); s[9]=fmaxf(b,0.f);
    }

    // ---- layer 2: feat = relu(h @ W2 + b2), 6 outputs = 3 f32x2 accumulators ----
    ulonglong2 c01 = *(const ulonglong2*)(wts + jb + 212);
    u64        c2  = *(const u64*)       (wts + jb + 216);
    u64 f0=c01.x, f1=c01.y, f2=c2;

    #pragma unroll
    for (int k = 0; k < 10; k++) {
        ulonglong2 v01 = *(const ulonglong2*)(wts + jb + 132 + k*8);
        u64        v2  = *(const u64*)       (wts + jb + 136 + k*8);
        u64 dk = pk(s[k], s[k]);
        f0 = ffma2(dk, v01.x, f0); f1 = ffma2(dk, v01.y, f1); f2 = ffma2(dk, v2, f2);
    }

    {
        float a, b;
        upk(f0,a,b); pf[0]=fmaxf(a,0.f); pf[1]=fmaxf(b,0.f);
        upk(f1,a,b); pf[2]=fmaxf(a,0.f); pf[3]=fmaxf(b,0.f);
        upk(f2,a,b); pf[4]=fmaxf(a,0.f); pf[5]=fmaxf(b,0.f);
    }

    // stage feat into this phase's buffer slot (cols 6J or 6(J-12))
    constexpr int SLOT = (J < 12) ? 6*J : 6*(J-12);
    *(float2*)(row + SLOT)     = make_float2(pf[0], pf[1]);
    *(float2*)(row + SLOT + 2) = make_float2(pf[2], pf[3]);
    *(float2*)(row + SLOT + 4) = make_float2(pf[4], pf[5]);
}

__device__ __forceinline__ void flush_half(const float* __restrict__ buf,
                                           float* __restrict__ ob, int base, int tid)
{
    // 256 elems x 72 floats = 4608 float4; consecutive tid -> consecutive gmem
    #pragma unroll
    for (int w = 0; w < 18; w++) {
        int n = tid + w * THREADS;
        int e = n / 18, c4 = n - e * 18;
        const float* s = buf + e * RS + c4 * 4;
        float2 lo = *(const float2*)s;
        float2 hi = *(const float2*)(s + 2);
        *(float4*)(ob + (size_t)e * 144 + base + c4 * 4) =
            make_float4(lo.x, lo.y, hi.x, hi.y);
    }
}

__global__ void __launch_bounds__(THREADS, 2)
se_kernel(const float* __restrict__ quat, const float* __restrict__ W1a,
          const float* __restrict__ W1b, const float* __restrict__ b1,
          const float* __restrict__ W2,  const float* __restrict__ b2,
          float* __restrict__ out)
{
    extern __shared__ float smem[];
    float* buf = smem;                     // [256][RS] = 75,776 B
    float* wts = smem + THREADS * RS;      // [NJ*WJ]   = 21,504 B (16B-aligned)
    const int tid = threadIdx.x;

    // ---- stage weights into padded smem layout ----
    for (int i = tid; i < NJ * WJ; i += THREADS) {
        int j = i / WJ, o = i - j * WJ;
        float v = 0.f;
        if (o < 120) {
            int r = o / 12, k = o - r * 12;
            if (k < 10) v = (r < 4) ? W1a[j*40 + r*10 + k] : W1b[j*60 + (r-4)*10 + k];
        } else if (o < 132) {
            int t = o - 120; if (t < 10) v = b1[j*10 + t];
        } else if (o < 212) {
            int t = o - 132; int k = t / 8, c = t - k * 8;
            if (c < 6) v = W2[j*60 + k*6 + c];
        } else if (o < 220) {
            int t = o - 212; if (t < 6) v = b2[j*6 + t];
        }
        wts[i] = v;
    }
    __syncthreads();

    const int e = blockIdx.x * THREADS + tid;
    const float4* q4 = (const float4*)(quat + (size_t)e * 96);
    float* row = buf + tid * RS;
    float* ob  = out + (size_t)blockIdx.x * THREADS * 144;

    float pf[6], s0[6], s9[6];

    // ---- phase 1: joints 0..11 (DFS; parent feats in registers) ----
    joint_step< 0, true >(wts, q4, row, pf);
    #pragma unroll
    for (int c = 0; c < 6; c++) s0[c] = pf[c];
    joint_step< 1, false>(wts, q4, row, pf);
    joint_step< 4, false>(wts, q4, row, pf);
    joint_step< 7, false>(wts, q4, row, pf);
    joint_step<10, false>(wts, q4, row, pf);
    #pragma unroll
    for (int c = 0; c < 6; c++) pf[c] = s0[c];
    joint_step< 2, false>(wts, q4, row, pf);
    joint_step< 5, false>(wts, q4, row, pf);
    joint_step< 8, false>(wts, q4, row, pf);
    joint_step<11, false>(wts, q4, row, pf);
    #pragma unroll
    for (int c = 0; c < 6; c++) pf[c] = s0[c];
    joint_step< 3, false>(wts, q4, row, pf);
    joint_step< 6, false>(wts, q4, row, pf);
    joint_step< 9, false>(wts, q4, row, pf);
    #pragma unroll
    for (int c = 0; c < 6; c++) s9[c] = pf[c];

    __syncthreads();                       // all phase-1 STS visible
    flush_half(buf, ob, 0, tid);           // out cols 0..71 (9 full sectors/elem)
    __syncthreads();                       // flush reads done before reuse

    // ---- phase 2: joints 12..23 ----
    joint_step<12, false>(wts, q4, row, pf);   // pf == s9 (joint 9 feat)
    joint_step<15, false>(wts, q4, row, pf);
    #pragma unroll
    for (int c = 0; c < 6; c++) pf[c] = s9[c];
    joint_step<13, false>(wts, q4, row, pf);
    joint_step<16, false>(wts, q4, row, pf);
    joint_step<18, false>(wts, q4, row, pf);
    joint_step<20, false>(wts, q4, row, pf);
    joint_step<22, false>(wts, q4, row, pf);
    #pragma unroll
    for (int c = 0; c < 6; c++) pf[c] = s9[c];
    joint_step<14, false>(wts, q4, row, pf);
    joint_step<17, false>(wts, q4, row, pf);
    joint_step<19, false>(wts, q4, row, pf);
    joint_step<21, false>(wts, q4, row, pf);
    joint_step<23, false>(wts, q4, row, pf);

    __syncthreads();
    flush_half(buf, ob, 72, tid);          // out cols 72..143
}

extern "C" void kernel_launch(void* const* d_in, const int* in_sizes, int n_in,
                              void* d_out, int out_size)
{
    const float* quat = (const float*)d_in[0];
    const float* W1a  = (const float*)d_in[1];
    const float* W1b  = (const float*)d_in[2];
    const float* b1   = (const float*)d_in[3];
    const float* W2   = (const float*)d_in[4];
    const float* b2   = (const float*)d_in[5];
    float* out = (float*)d_out;

    int B = in_sizes[0] / 96;              // quat = B * 24 * 4 floats
    int blocks = B / THREADS;              // 524288 / 256 = 2048

    size_t smem_bytes = (size_t)(THREADS * RS + NJ * WJ) * sizeof(float); // 97,280
    cudaFuncSetAttribute(se_kernel, cudaFuncAttributeMaxDynamicSharedMemorySize,
                         (int)smem_bytes);

    se_kernel<<<blocks, THREADS, smem_bytes>>>(quat, W1a, W1b, b1, W2, b2, out);
}

// round 7
// speedup vs baseline: 2.2726x; 1.2782x over previous
#include <cuda_runtime.h>

// StructureEncoder: B=524288 elems, 24-joint tree of tiny MLPs (10->10->6).
// R7: E=2 elems/thread (halves per-elem weight-LDS, the R4 81% L1tex binder)
// + SIX-phase smem output stager: flush every 4 joints (24 floats = 96B = 3
// full sectors per elem, all chunk bases 32B-aligned -> no L2 RMW). Stager is
// TILE x 26 floats -> 74.75KB/CTA -> 2 CTAs x 256 thr = 16 warps/SM.
// fma.rn.f32x2 packed math; padded smem weights load directly as u64 pairs.

#define THREADS 256
#define TILE    512      // elems per CTA (E=2)
#define RS      26       // floats per elem row in stager (24 data + 2 pad)
#define WJ      224      // padded weight floats per joint
#define NJ      24

typedef unsigned long long u64;

__device__ __forceinline__ u64 pk(float a, float b) {
    u64 r; asm("mov.b64 %0,{%1,%2};" : "=l"(r) : "f"(a), "f"(b)); return r;
}
__device__ __forceinline__ void upk(u64 v, float& a, float& b) {
    asm("mov.b64 {%0,%1},%2;" : "=f"(a), "=f"(b) : "l"(v));
}
__device__ __forceinline__ u64 ffma2(u64 a, u64 b, u64 c) {
    u64 d; asm("fma.rn.f32x2 %0,%1,%2,%3;" : "=l"(d) : "l"(a), "l"(b), "l"(c)); return d;
}

// Padded per-joint weight block in smem (base = j*WJ floats, 16B-aligned):
//   [  0..119]  W1 rows r=0..9 (r<4: W1a row r, else W1b row r-4), 12 floats/row
//   [120..131]  b1 (10 + 2 pad)
//   [132..211]  W2 rows k=0..9, 8 floats/row (6 data + 2 pad)
//   [212..219]  b2 (6 + 2 pad)

template<int J, int BASE, bool ROOT>
__device__ __forceinline__ void joint_step(const float* __restrict__ wts,
                                           const float4* __restrict__ qA4,
                                           const float4* __restrict__ qB4,
                                           float* __restrict__ rowA,
                                           float* __restrict__ rowB,
                                           float (&pfA)[6], float (&pfB)[6])
{
    const int jb = J * WJ;
    float4 qa = qA4[J];
    float4 qb = qB4[J];

    float xA[10], xB[10];
    xA[0]=qa.x; xA[1]=qa.y; xA[2]=qa.z; xA[3]=qa.w;
    xB[0]=qb.x; xB[1]=qb.y; xB[2]=qb.z; xB[3]=qb.w;
    if (!ROOT) {
        #pragma unroll
        for (int c = 0; c < 6; c++) { xA[4+c] = pfA[c]; xB[4+c] = pfB[c]; }
    }

    // ---- layer 1: h = relu(x @ W1 + b1), 10 outputs = 5 f32x2 accumulators ----
    ulonglong2 bA = *(const ulonglong2*)(wts + jb + 120);
    ulonglong2 bB = *(const ulonglong2*)(wts + jb + 124);
    u64        bC = *(const u64*)       (wts + jb + 128);
    u64 hA0=bA.x, hA1=bA.y, hA2=bB.x, hA3=bB.y, hA4=bC;
    u64 hB0=bA.x, hB1=bA.y, hB2=bB.x, hB3=bB.y, hB4=bC;

    const int NR = ROOT ? 4 : 10;
    #pragma unroll
    for (int r = 0; r < NR; r++) {
        ulonglong2 wAB = *(const ulonglong2*)(wts + jb + r*12);
        ulonglong2 wCD = *(const ulonglong2*)(wts + jb + r*12 + 4);
        u64        wE  = *(const u64*)       (wts + jb + r*12 + 8);
        u64 xa = pk(xA[r], xA[r]);
        hA0 = ffma2(xa, wAB.x, hA0); hA1 = ffma2(xa, wAB.y, hA1);
        hA2 = ffma2(xa, wCD.x, hA2); hA3 = ffma2(xa, wCD.y, hA3);
        hA4 = ffma2(xa, wE,    hA4);
        u64 xb = pk(xB[r], xB[r]);
        hB0 = ffma2(xb, wAB.x, hB0); hB1 = ffma2(xb, wAB.y, hB1);
        hB2 = ffma2(xb, wCD.x, hB2); hB3 = ffma2(xb, wCD.y, hB3);
        hB4 = ffma2(xb, wE,    hB4);
    }

    float sA[10], sB[10];
    {
        float a, b;
        upk(hA0,a,b); sA[0]=fmaxf(a,0.f); sA[1]=fmaxf(b,0.f);
        upk(hA1,a,b); sA[2]=fmaxf(a,0.f); sA[3]=fmaxf(b,0.f);
        upk(hA2,a,b); sA[4]=fmaxf(a,0.f); sA[5]=fmaxf(b,0.f);
        upk(hA3,a,b); sA[6]=fmaxf(a,0.f); sA[7]=fmaxf(b,0.f);
        upk(hA4,a,b); sA[8]=fmaxf(a,0.f); sA[9]=fmaxf(b,0.f);
        upk(hB0,a,b); sB[0]=fmaxf(a,0.f); sB[1]=fmaxf(b,0.f);
        upk(hB1,a,b); sB[2]=fmaxf(a,0.f); sB[3]=fmaxf(b,0.f);
        upk(hB2,a,b); sB[4]=fmaxf(a,0.f); sB[5]=fmaxf(b,0.f);
        upk(hB3,a,b); sB[6]=fmaxf(a,0.f); sB[7]=fmaxf(b,0.f);
        upk(hB4,a,b); sB[8]=fmaxf(a,0.f); sB[9]=fmaxf(b,0.f);
    }

    // ---- layer 2: feat = relu(h @ W2 + b2), 6 outputs = 3 f32x2 accumulators ----
    ulonglong2 c01 = *(const ulonglong2*)(wts + jb + 212);
    u64        c2  = *(const u64*)       (wts + jb + 216);
    u64 fA0=c01.x, fA1=c01.y, fA2=c2;
    u64 fB0=c01.x, fB1=c01.y, fB2=c2;

    #pragma unroll
    for (int k = 0; k < 10; k++) {
        ulonglong2 v01 = *(const ulonglong2*)(wts + jb + 132 + k*8);
        u64        v2  = *(const u64*)       (wts + jb + 136 + k*8);
        u64 da = pk(sA[k], sA[k]);
        fA0 = ffma2(da, v01.x, fA0); fA1 = ffma2(da, v01.y, fA1); fA2 = ffma2(da, v2, fA2);
        u64 db = pk(sB[k], sB[k]);
        fB0 = ffma2(db, v01.x, fB0); fB1 = ffma2(db, v01.y, fB1); fB2 = ffma2(db, v2, fB2);
    }

    {
        float a, b;
        upk(fA0,a,b); pfA[0]=fmaxf(a,0.f); pfA[1]=fmaxf(b,0.f);
        upk(fA1,a,b); pfA[2]=fmaxf(a,0.f); pfA[3]=fmaxf(b,0.f);
        upk(fA2,a,b); pfA[4]=fmaxf(a,0.f); pfA[5]=fmaxf(b,0.f);
        upk(fB0,a,b); pfB[0]=fmaxf(a,0.f); pfB[1]=fmaxf(b,0.f);
        upk(fB1,a,b); pfB[2]=fmaxf(a,0.f); pfB[3]=fmaxf(b,0.f);
        upk(fB2,a,b); pfB[4]=fmaxf(a,0.f); pfB[5]=fmaxf(b,0.f);
    }

    constexpr int SLOT = 6 * (J - BASE);
    *(float2*)(rowA + SLOT)     = make_float2(pfA[0], pfA[1]);
    *(float2*)(rowA + SLOT + 2) = make_float2(pfA[2], pfA[3]);
    *(float2*)(rowA + SLOT + 4) = make_float2(pfA[4], pfA[5]);
    *(float2*)(rowB + SLOT)     = make_float2(pfB[0], pfB[1]);
    *(float2*)(rowB + SLOT + 2) = make_float2(pfB[2], pfB[3]);
    *(float2*)(rowB + SLOT + 4) = make_float2(pfB[4], pfB[5]);
}

__device__ __forceinline__ void flush_quarter(const float* __restrict__ buf,
                                              float* __restrict__ ob, int base, int tid)
{
    // TILE elems x 24 floats = 3072 float4; consecutive n -> contiguous gmem
    #pragma unroll
    for (int w = 0; w < 12; w++) {
        int n = tid + w * THREADS;
        int e = n / 6, c4 = n - e * 6;
        const float* s = buf + e * RS + c4 * 4;
        float2 lo = *(const float2*)s;
        float2 hi = *(const float2*)(s + 2);
        *(float4*)(ob + (size_t)e * 144 + base + c4 * 4) =
            make_float4(lo.x, lo.y, hi.x, hi.y);
    }
}

#define SAVE6(dst, src)  { _Pragma("unroll") for (int c = 0; c < 6; c++) dst[c] = src[c]; }

__global__ void __launch_bounds__(THREADS, 2)
se_kernel(const float* __restrict__ quat, const float* __restrict__ W1a,
          const float* __restrict__ W1b, const float* __restrict__ b1,
          const float* __restrict__ W2,  const float* __restrict__ b2,
          float* __restrict__ out)
{
    extern __shared__ float smem[];
    float* buf = smem;                     // [TILE][RS] = 53,248 B
    float* wts = smem + TILE * RS;         // [NJ*WJ]    = 21,504 B (16B-aligned)
    const int tid = threadIdx.x;

    // ---- stage weights into padded smem layout ----
    for (int i = tid; i < NJ * WJ; i += THREADS) {
        int j = i / WJ, o = i - j * WJ;
        float v = 0.f;
        if (o < 120) {
            int r = o / 12, k = o - r * 12;
            if (k < 10) v = (r < 4) ? W1a[j*40 + r*10 + k] : W1b[j*60 + (r-4)*10 + k];
        } else if (o < 132) {
            int t = o - 120; if (t < 10) v = b1[j*10 + t];
        } else if (o < 212) {
            int t = o - 132; int k = t / 8, c = t - k * 8;
            if (c < 6) v = W2[j*60 + k*6 + c];
        } else if (o < 220) {
            int t = o - 212; if (t < 6) v = b2[j*6 + t];
        }
        wts[i] = v;
    }
    __syncthreads();

    const int eA = blockIdx.x * TILE + tid;
    const int eB = eA + THREADS;
    const float4* qA4 = (const float4*)(quat + (size_t)eA * 96);
    const float4* qB4 = (const float4*)(quat + (size_t)eB * 96);
    float* rowA = buf + tid * RS;
    float* rowB = buf + (tid + THREADS) * RS;
    float* ob   = out + (size_t)blockIdx.x * TILE * 144;

    float pfA[6], pfB[6];
    float t0A[6], t0B[6], t1A[6], t1B[6], t2A[6], t2B[6], t3A[6], t3B[6];

    // ---- G1: joints 0,1,2,3 (out cols 0..23) ----
    joint_step< 0,  0, true >(wts, qA4, qB4, rowA, rowB, pfA, pfB);
    SAVE6(t0A, pfA); SAVE6(t0B, pfB);                       // t0 = f0
    joint_step< 1,  0, false>(wts, qA4, qB4, rowA, rowB, pfA, pfB);
    SAVE6(t1A, pfA); SAVE6(t1B, pfB);                       // t1 = f1
    SAVE6(pfA, t0A); SAVE6(pfB, t0B);
    joint_step< 2,  0, false>(wts, qA4, qB4, rowA, rowB, pfA, pfB);
    SAVE6(t2A, pfA); SAVE6(t2B, pfB);                       // t2 = f2
    SAVE6(pfA, t0A); SAVE6(pfB, t0B);
    joint_step< 3,  0, false>(wts, qA4, qB4, rowA, rowB, pfA, pfB);
    SAVE6(t3A, pfA); SAVE6(t3B, pfB);                       // t3 = f3
    __syncthreads(); flush_quarter(buf, ob, 0, tid); __syncthreads();

    // ---- G2: joints 4,7,5,6 (out cols 24..47) ----
    SAVE6(pfA, t1A); SAVE6(pfB, t1B);                       // f1
    joint_step< 4,  4, false>(wts, qA4, qB4, rowA, rowB, pfA, pfB);
    joint_step< 7,  4, false>(wts, qA4, qB4, rowA, rowB, pfA, pfB);
    SAVE6(t1A, pfA); SAVE6(t1B, pfB);                       // t1 = f7
    SAVE6(pfA, t2A); SAVE6(pfB, t2B);                       // f2
    joint_step< 5,  4, false>(wts, qA4, qB4, rowA, rowB, pfA, pfB);
    SAVE6(t2A, pfA); SAVE6(t2B, pfB);                       // t2 = f5
    SAVE6(pfA, t3A); SAVE6(pfB, t3B);                       // f3
    joint_step< 6,  4, false>(wts, qA4, qB4, rowA, rowB, pfA, pfB);
    SAVE6(t3A, pfA); SAVE6(t3B, pfB);                       // t3 = f6
    __syncthreads(); flush_quarter(buf, ob, 24, tid); __syncthreads();

    // ---- G3: joints 8,11,9,10 (out cols 48..71) ----
    SAVE6(pfA, t2A); SAVE6(pfB, t2B);                       // f5
    joint_step< 8,  8, false>(wts, qA4, qB4, rowA, rowB, pfA, pfB);
    joint_step<11,  8, false>(wts, qA4, qB4, rowA, rowB, pfA, pfB);
    SAVE6(pfA, t3A); SAVE6(pfB, t3B);                       // f6
    joint_step< 9,  8, false>(wts, qA4, qB4, rowA, rowB, pfA, pfB);
    SAVE6(t2A, pfA); SAVE6(t2B, pfB);                       // t2 = f9
    SAVE6(pfA, t1A); SAVE6(pfB, t1B);                       // f7
    joint_step<10,  8, false>(wts, qA4, qB4, rowA, rowB, pfA, pfB);
    __syncthreads(); flush_quarter(buf, ob, 48, tid); __syncthreads();

    // ---- G4: joints 12,15,13,14 (out cols 72..95) ----
    SAVE6(pfA, t2A); SAVE6(pfB, t2B);                       // f9
    joint_step<12, 12, false>(wts, qA4, qB4, rowA, rowB, pfA, pfB);
    joint_step<15, 12, false>(wts, qA4, qB4, rowA, rowB, pfA, pfB);
    SAVE6(pfA, t2A); SAVE6(pfB, t2B);                       // f9
    joint_step<13, 12, false>(wts, qA4, qB4, rowA, rowB, pfA, pfB);
    SAVE6(t0A, pfA); SAVE6(t0B, pfB);                       // t0 = f13
    SAVE6(pfA, t2A); SAVE6(pfB, t2B);                       // f9
    joint_step<14, 12, false>(wts, qA4, qB4, rowA, rowB, pfA, pfB);
    SAVE6(t1A, pfA); SAVE6(t1B, pfB);                       // t1 = f14
    __syncthreads(); flush_quarter(buf, ob, 72, tid); __syncthreads();

    // ---- G5: joints 16,18,17,19 (out cols 96..119) ----
    SAVE6(pfA, t0A); SAVE6(pfB, t0B);                       // f13
    joint_step<16, 16, false>(wts, qA4, qB4, rowA, rowB, pfA, pfB);
    joint_step<18, 16, false>(wts, qA4, qB4, rowA, rowB, pfA, pfB);
    SAVE6(t0A, pfA); SAVE6(t0B, pfB);                       // t0 = f18
    SAVE6(pfA, t1A); SAVE6(pfB, t1B);                       // f14
    joint_step<17, 16, false>(wts, qA4, qB4, rowA, rowB, pfA, pfB);
    joint_step<19, 16, false>(wts, qA4, qB4, rowA, rowB, pfA, pfB);
    SAVE6(t1A, pfA); SAVE6(t1B, pfB);                       // t1 = f19
    __syncthreads(); flush_quarter(buf, ob, 96, tid); __syncthreads();

    // ---- G6: joints 20,22,21,23 (out cols 120..143) ----
    SAVE6(pfA, t0A); SAVE6(pfB, t0B);                       // f18
    joint_step<20, 20, false>(wts, qA4, qB4, rowA, rowB, pfA, pfB);
    joint_step<22, 20, false>(wts, qA4, qB4, rowA, rowB, pfA, pfB);
    SAVE6(pfA, t1A); SAVE6(pfB, t1B);                       // f19
    joint_step<21, 20, false>(wts, qA4, qB4, rowA, rowB, pfA, pfB);
    joint_step<23, 20, false>(wts, qA4, qB4, rowA, rowB, pfA, pfB);
    __syncthreads(); flush_quarter(buf, ob, 120, tid);
}

extern "C" void kernel_launch(void* const* d_in, const int* in_sizes, int n_in,
                              void* d_out, int out_size)
{
    const float* quat = (const float*)d_in[0];
    const float* W1a  = (const float*)d_in[1];
    const float* W1b  = (const float*)d_in[2];
    const float* b1   = (const float*)d_in[3];
    const float* W2   = (const float*)d_in[4];
    const float* b2   = (const float*)d_in[5];
    float* out = (float*)d_out;

    int B = in_sizes[0] / 96;              // quat = B * 24 * 4 floats
    int blocks = B / TILE;                 // 524288 / 512 = 1024

    size_t smem_bytes = (size_t)(TILE * RS + NJ * WJ) * sizeof(float); // 74,752
    cudaFuncSetAttribute(se_kernel, cudaFuncAttributeMaxDynamicSharedMemorySize,
                         (int)smem_bytes);

    se_kernel<<<blocks, THREADS, smem_bytes>>>(quat, W1a, W1b, b1, W2, b2, out);
}